// round 12
// baseline (speedup 1.0000x reference)
#include <cuda_runtime.h>
#include <math.h>
#include <stdint.h>

#define NN 30000
#define EE 510000      // 30000*16 + 30000 self loops
#define TT 2
#define KDIM 128       // F_IN == H1 == 128 (GEMM K for both layers)

// ---------------- scratch (device globals; no allocation allowed) ----------------
__device__ float  g_h[(size_t)NN * 256];     // GEMM output t0
__device__ float  g_h2[(size_t)NN * 256];    // GEMM output t1
__device__ float  g_mu0[(size_t)NN * 128];
__device__ float  g_mu1[(size_t)NN * 128];
__device__ float  g_si[TT][NN];
__device__ float  g_sj[TT][NN];
__device__ float  g_watt[2][128];            // W @ att halves (current layer)
__device__ float  g_invdeg[TT][NN];
__device__ int    g_deg[TT][NN];
__device__ int    g_rowptr[TT][NN + 1];
__device__ int    g_woff[TT][NN];
__device__ int    g_csrc[TT][EE];
__device__ double g_acc[8];  // [0..3] ixz sums, [4..7] skl sums

// ---------------- helpers ----------------
__device__ __forceinline__ float blockReduceSum(float v, float* sm) {
    int lane = threadIdx.x & 31, wid = threadIdx.x >> 5;
#pragma unroll
    for (int o = 16; o; o >>= 1) v += __shfl_down_sync(0xffffffffu, v, o);
    if (lane == 0) sm[wid] = v;
    __syncthreads();
    int nw = (blockDim.x + 31) >> 5;
    v = (threadIdx.x < nw) ? sm[threadIdx.x] : 0.f;
    if (wid == 0) {
#pragma unroll
        for (int o = 16; o; o >>= 1) v += __shfl_down_sync(0xffffffffu, v, o);
    }
    return v;  // valid on thread 0
}

__device__ __forceinline__ uint32_t f2tf32(float f) {
    uint32_t u;
    asm("cvt.rna.tf32.f32 %0, %1;" : "=r"(u) : "f"(f));
    return u;
}

// ---------------- setup kernels ----------------
__global__ void zero_kernel() {
    int i = blockIdx.x * blockDim.x + threadIdx.x;
    if (i < TT * NN) (&g_deg[0][0])[i] = 0;
    if (i < 8) g_acc[i] = 0.0;
}

__global__ void hist_kernel(const int* __restrict__ ei) {
    int t = blockIdx.y;
    int e = blockIdx.x * blockDim.x + threadIdx.x;
    const int* dst = ei + (size_t)t * 2 * EE + EE;
    if (e < EE) atomicAdd(&g_deg[t][dst[e]], 1);
}

__global__ void scan_kernel() {
    int t = blockIdx.x;
    const int T = 1024;
    int tid = threadIdx.x;
    const int chunk = (NN + T - 1) / T;  // 30
    int s0 = tid * chunk;
    int sum = 0;
    for (int i = 0; i < chunk; i++) {
        int idx = s0 + i;
        if (idx < NN) sum += g_deg[t][idx];
    }
    int lane = tid & 31, wid = tid >> 5;
    int v = sum;
#pragma unroll
    for (int o = 1; o < 32; o <<= 1) {
        int u = __shfl_up_sync(0xffffffffu, v, o);
        if (lane >= o) v += u;
    }
    __shared__ int ws[32];
    if (lane == 31) ws[wid] = v;
    __syncthreads();
    if (wid == 0) {
        int w = ws[lane];
#pragma unroll
        for (int o = 1; o < 32; o <<= 1) {
            int u = __shfl_up_sync(0xffffffffu, w, o);
            if (lane >= o) w += u;
        }
        ws[lane] = w;
    }
    __syncthreads();
    int excl = (v - sum) + (wid > 0 ? ws[wid - 1] : 0);
    int run = excl;
    for (int i = 0; i < chunk; i++) {
        int idx = s0 + i;
        if (idx < NN) {
            int d = g_deg[t][idx];
            g_rowptr[t][idx] = run;
            g_woff[t][idx] = run;
            g_invdeg[t][idx] = 1.0f / (float)d;
            run += d;
        }
    }
    if (tid == T - 1) g_rowptr[t][NN] = run;
}

__global__ void scatter_kernel(const int* __restrict__ ei) {
    int t = blockIdx.y;
    int e = blockIdx.x * blockDim.x + threadIdx.x;
    const int* src = ei + (size_t)t * 2 * EE;
    const int* dst = src + EE;
    if (e < EE) {
        int d = dst[e];
        int pos = atomicAdd(&g_woff[t][d], 1);
        g_csrc[t][pos] = src[e];
    }
}

// ---------------- TF32 tensor-core GEMM (pipelined) ------------------------------
// C[M,Ncols] = A[M,128] * B[128,Ncols].  Tile 128x64, 256 threads, 8 warps of 32x32.
// B tile [128][64] loaded ONCE (full K) transposed+tf32 into smem.
// A tile double-buffered via cp.async (raw fp32), tf32 cvt in registers.
// blockIdx.z selects (A0,C0) vs (A1,C1) — the two snapshots.
#define ASTR 36
#define BSTR 132
#define A_STAGE (128 * ASTR)
#define GEMM_SMEM ((2 * A_STAGE + 64 * BSTR) * 4)
__global__ void __launch_bounds__(256)
gemm_tc_kernel(const float* __restrict__ A0, const float* __restrict__ A1,
               const float* __restrict__ B, float* __restrict__ C0,
               float* __restrict__ C1, int M, int Ncols) {
    extern __shared__ float smem[];
    float* Bs = smem + 2 * A_STAGE;
    const float* A = blockIdx.z ? A1 : A0;
    float* C = blockIdx.z ? C1 : C0;
    int tid = threadIdx.x, lane = tid & 31, wid = tid >> 5;
    int warp_m = wid & 3, warp_n = wid >> 2;
    int row0 = blockIdx.y * 128, col0 = blockIdx.x * 64;
    int sub = lane >> 3, l8 = lane & 7;
    uint32_t as_base = (uint32_t)__cvta_generic_to_shared(smem);
    uint32_t bs_base = as_base + 2 * A_STAGE * 4;

    // B fill: full K, transposed, tf32-converted (one time)
    for (int i = tid; i < 128 * 64; i += 256) {
        int k = i >> 6, n = i & 63;
        Bs[n * BSTR + k] = __uint_as_float(f2tf32(B[(size_t)k * Ncols + col0 + n]));
    }

    // A stage fill via cp.async (4 x 16B per thread); OOB rows: clamped src + zfill
#define FILL_A(buf, k0)                                                              \
    {                                                                                \
        _Pragma("unroll") for (int i = 0; i < 4; i++) {                              \
            int idx = tid + i * 256;                                                 \
            int r = idx >> 3, kc = (idx & 7) * 4;                                    \
            uint32_t dstp = as_base + (uint32_t)(((buf) * A_STAGE + r * ASTR + kc) * 4); \
            int rr = row0 + r;                                                       \
            int ok = rr < M;                                                         \
            int rs = ok ? rr : (M - 1);                                              \
            const float* srcp = A + (size_t)rs * KDIM + (k0) + kc;                   \
            int sz = ok ? 16 : 0;                                                    \
            asm volatile("cp.async.ca.shared.global [%0], [%1], 16, %2;"             \
                         :: "r"(dstp), "l"(srcp), "r"(sz));                          \
        }                                                                            \
    }

    FILL_A(0, 0);
    asm volatile("cp.async.commit_group;");

    float acc[2][4][4] = {};
    int a_r = warp_m * 32 + (sub & 1) * 8 + l8;
    int a_c = (sub >> 1) * 4;
    int b_r = warp_n * 32 + (sub >> 1) * 8 + l8;
    int b_c = (sub & 1) * 4;

    int s = 0;
    for (int k0 = 0; k0 < KDIM; k0 += 32, s ^= 1) {
        if (k0 + 32 < KDIM) {
            FILL_A(s ^ 1, k0 + 32);
            asm volatile("cp.async.commit_group;");
            asm volatile("cp.async.wait_group 1;");
        } else {
            asm volatile("cp.async.wait_group 0;");
        }
        __syncthreads();
        int abase = s * A_STAGE;
#pragma unroll
        for (int kk = 0; kk < 32; kk += 8) {
            uint32_t a[2][4], b[2][4];
#pragma unroll
            for (int im = 0; im < 2; im++) {
                uint32_t addr = as_base + (uint32_t)((abase + (a_r + im * 16) * ASTR + a_c + kk) * 4);
                asm volatile("ldmatrix.sync.aligned.m8n8.x4.shared.b16 {%0,%1,%2,%3}, [%4];"
                             : "=r"(a[im][0]), "=r"(a[im][1]), "=r"(a[im][2]), "=r"(a[im][3])
                             : "r"(addr));
            }
#pragma unroll
            for (int im = 0; im < 2; im++)
#pragma unroll
                for (int j = 0; j < 4; j++)
                    a[im][j] = f2tf32(__uint_as_float(a[im][j]));
#pragma unroll
            for (int p = 0; p < 2; p++) {
                uint32_t addr = bs_base + (uint32_t)(((b_r + p * 16) * BSTR + b_c + k0 + kk) * 4);
                asm volatile("ldmatrix.sync.aligned.m8n8.x4.shared.b16 {%0,%1,%2,%3}, [%4];"
                             : "=r"(b[p][0]), "=r"(b[p][1]), "=r"(b[p][2]), "=r"(b[p][3])
                             : "r"(addr));
            }
#pragma unroll
            for (int im = 0; im < 2; im++)
#pragma unroll
                for (int in = 0; in < 4; in++) {
                    uint32_t b0 = b[in >> 1][(in & 1) * 2 + 0];
                    uint32_t b1 = b[in >> 1][(in & 1) * 2 + 1];
                    asm volatile(
                        "mma.sync.aligned.m16n8k8.row.col.f32.tf32.tf32.f32 "
                        "{%0,%1,%2,%3}, {%4,%5,%6,%7}, {%8,%9}, {%0,%1,%2,%3};"
                        : "+f"(acc[im][in][0]), "+f"(acc[im][in][1]),
                          "+f"(acc[im][in][2]), "+f"(acc[im][in][3])
                        : "r"(a[im][0]), "r"(a[im][1]), "r"(a[im][2]), "r"(a[im][3]),
                          "r"(b0), "r"(b1));
                }
        }
        __syncthreads();
    }
#pragma unroll
    for (int im = 0; im < 2; im++) {
        int r = row0 + warp_m * 32 + im * 16 + (lane >> 2);
#pragma unroll
        for (int in = 0; in < 4; in++) {
            int c = col0 + warp_n * 32 + in * 8 + (lane & 3) * 2;
            if (r < M)
                *(float2*)&C[(size_t)r * Ncols + c] = make_float2(acc[im][in][0], acc[im][in][1]);
            if (r + 8 < M)
                *(float2*)&C[(size_t)(r + 8) * Ncols + c] = make_float2(acc[im][in][2], acc[im][in][3]);
        }
    }
}

// ---------------- W @ att precompute ----------------
__global__ void watt_kernel(const float* __restrict__ W, const float* __restrict__ att, int TC) {
    int k = threadIdx.x;  // 0..127
    const float* row = W + (size_t)k * TC;
    float a = 0.f, b = 0.f;
    for (int c = 0; c < TC; c++) {
        float v = row[c];
        a = fmaf(v, att[c], a);
        b = fmaf(v, att[TC + c], b);
    }
    g_watt[0][k] = a;
    g_watt[1][k] = b;
}

// ---------------- per-node attention scores (both snapshots) ----------------
__global__ void scores_x_kernel(const float4* __restrict__ x0, const float4* __restrict__ x1) {
    int t = blockIdx.y;
    const float4* x4 = t ? x1 : x0;
    int gw = (blockIdx.x * blockDim.x + threadIdx.x) >> 5;
    int lane = threadIdx.x & 31;
    if (gw >= NN) return;
    float4 v = x4[(size_t)gw * 32 + lane];
    const float4 wa = *(const float4*)&g_watt[0][lane * 4];
    const float4 wb = *(const float4*)&g_watt[1][lane * 4];
    float a = v.x * wa.x + v.y * wa.y + v.z * wa.z + v.w * wa.w;
    float b = v.x * wb.x + v.y * wb.y + v.z * wb.z + v.w * wb.w;
#pragma unroll
    for (int o = 16; o; o >>= 1) {
        a += __shfl_down_sync(0xffffffffu, a, o);
        b += __shfl_down_sync(0xffffffffu, b, o);
    }
    if (lane == 0) {
        g_si[t][gw] = a;
        g_sj[t][gw] = b;
    }
}

// ---------------- aggregation (alpha + skl fused) + KL epilogue -------------------
// One block per (node, snapshot); 2C threads, one per output channel.
// alpha computed in-block: dst == n, so si[dst] is uniform; only sj[src] gathers.
template <int C>
__global__ void agg_kernel(const float* __restrict__ h0, const float* __restrict__ h1,
                           const float* __restrict__ bias, float* __restrict__ out0,
                           float* __restrict__ out1, double* __restrict__ ixz_base,
                           double* __restrict__ skl_base) {
    constexpr int TC = 2 * C;
    __shared__ float s_alpha[TC];
    __shared__ int s_src[TC];
    __shared__ float s_std[C];
    __shared__ float s_red[32];
    int n = blockIdx.x, t = blockIdx.y, tid = threadIdx.x;
    const float* h = t ? h1 : h0;
    const float* sj = g_sj[t];
    const int* csrc = g_csrc[t];
    float* mu_out = t ? out1 : out0;
    int start = g_rowptr[t][n], end = g_rowptr[t][n + 1];
    float si_n = g_si[t][n], inv = g_invdeg[t][n];
    const float q = 1.f / (1.f + expf(-1.f / 15.f));
    const float lq = logf(q), l1q = logf(1.f - q);
    float acc = 0.f, skl_loc = 0.f;
    for (int base = start; base < end; base += TC) {
        int cnt = min(TC, end - base);
        if (tid < cnt) {
            int s = csrc[base + tid];
            float l = si_n + sj[s];
            l = l > 0.f ? l : 0.2f * l;
            float p = 1.f / (1.f + expf(-l));
            p = fminf(fmaxf(p, 0.01f), 0.99f);
            s_alpha[tid] = p * inv;
            s_src[tid] = s;
            skl_loc += p * (logf(p) - lq) + (1.f - p) * (logf(1.f - p) - l1q);
        }
        __syncthreads();
        for (int i = 0; i < cnt; i++)
            acc = fmaf(s_alpha[i], h[(size_t)s_src[i] * TC + tid], acc);
        __syncthreads();
    }
    acc += bias[tid];
    if (tid >= C) {
        float x = acc;
        s_std[tid - C] = fmaxf(x, 0.f) + log1pf(expf(-fabsf(x))) + 1e-10f;
    }
    __syncthreads();
    float kl = 0.f;
    if (tid < C) {
        float mu = acc, sd = s_std[tid];
        kl = -logf(sd) + 0.5f * fmaf(sd, sd, mu * mu) - 0.5f;
        mu_out[(size_t)n * C + tid] = mu;
    }
    float t1 = blockReduceSum(kl, s_red);
    if (tid == 0) atomicAdd(ixz_base + t, (double)t1);
    __syncthreads();
    float t2 = blockReduceSum(skl_loc, s_red);
    if (tid == 0) atomicAdd(skl_base + t, (double)t2);
}

// ---------------- temporal fusion / activations ----------------
__global__ void fuse1_kernel() {
    int i = blockIdx.x * blockDim.x + threadIdx.x;
    if (i < NN * 128) {
        float m0 = g_mu0[i], m1 = g_mu1[i];
        g_mu1[i] = fmaxf(0.4f * m0 + 0.2f * m1, 0.f);
        g_mu0[i] = fmaxf(m0, 0.f);
    }
}

__global__ void fuse2_kernel(float* __restrict__ out) {
    int i = blockIdx.x * blockDim.x + threadIdx.x;
    if (i < NN * 64) out[NN * 64 + i] = 0.4f * out[i] + 0.2f * g_mu1[i];
}

__global__ void finalize_kernel(float* __restrict__ out, int out_size) {
    double ixz = (g_acc[0] + g_acc[1] + g_acc[2] + g_acc[3]) / (4.0 * (double)NN);
    double skl = (g_acc[4] + g_acc[5] + g_acc[6] + g_acc[7]) / (4.0 * (double)EE);
    out[out_size - 2] = (float)ixz;
    out[out_size - 1] = (float)skl;
}

// ---------------- launch ----------------
extern "C" void kernel_launch(void* const* d_in, const int* in_sizes, int n_in,
                              void* d_out, int out_size) {
    const float* x_all = (const float*)d_in[0];   // [T, N, 128]
    const int* ei = (const int*)d_in[1];          // [T, 2, E]
    const float* W1 = (const float*)d_in[2];      // [128, 256]
    const float* att1 = (const float*)d_in[3];    // [512]
    const float* b1 = (const float*)d_in[4];      // [256]
    const float* W2 = (const float*)d_in[5];      // [128, 128]
    const float* att2 = (const float*)d_in[6];    // [256]
    const float* b2 = (const float*)d_in[7];      // [128]
    float* out = (float*)d_out;

    (void)cudaFuncSetAttribute(gemm_tc_kernel,
                               cudaFuncAttributeMaxDynamicSharedMemorySize, GEMM_SMEM);

    float *p_h, *p_h2, *p_mu0, *p_mu1;
    double* p_acc;
    cudaGetSymbolAddress((void**)&p_h, g_h);
    cudaGetSymbolAddress((void**)&p_h2, g_h2);
    cudaGetSymbolAddress((void**)&p_mu0, g_mu0);
    cudaGetSymbolAddress((void**)&p_mu1, g_mu1);
    cudaGetSymbolAddress((void**)&p_acc, g_acc);

    const int EB = (EE + 255) / 256;
    const int SB = (NN * 32 + 255) / 256;
    const int MB = (NN + 127) / 128;  // 235

    zero_kernel<<<(TT * NN + 255) / 256, 256>>>();                        // 0
    hist_kernel<<<dim3(EB, 2), 256>>>(ei);                                // 1
    scan_kernel<<<2, 1024>>>();                                           // 2
    gemm_tc_kernel<<<dim3(4, MB, 2), 256, GEMM_SMEM>>>(                   // 3 <- profiled
        x_all, x_all + (size_t)NN * KDIM, W1, p_h, p_h2, NN, 256);
    scatter_kernel<<<dim3(EB, 2), 256>>>(ei);                             // 4
    watt_kernel<<<1, 128>>>(W1, att1, 256);                               // 5
    scores_x_kernel<<<dim3(SB, 2), 256>>>(                                // 6
        (const float4*)x_all, (const float4*)(x_all + (size_t)NN * KDIM));
    agg_kernel<128><<<dim3(NN, 2), 256>>>(p_h, p_h2, b1, p_mu0, p_mu1,    // 7
                                          p_acc + 0, p_acc + 4);
    fuse1_kernel<<<(NN * 128 + 255) / 256, 256>>>();                      // 8

    watt_kernel<<<1, 128>>>(W2, att2, 128);                               // 9
    gemm_tc_kernel<<<dim3(2, MB, 2), 256, GEMM_SMEM>>>(                   // 10
        p_mu0, p_mu1, W2, p_h, p_h2, NN, 128);
    scores_x_kernel<<<dim3(SB, 2), 256>>>((const float4*)p_mu0, (const float4*)p_mu1);  // 11
    agg_kernel<64><<<dim3(NN, 2), 128>>>(p_h, p_h2, b2, out, p_mu1,       // 12
                                         p_acc + 2, p_acc + 6);
    fuse2_kernel<<<(NN * 64 + 255) / 256, 256>>>(out);                    // 13
    finalize_kernel<<<1, 1>>>(out, out_size);                             // 14
}

// round 13
// speedup vs baseline: 1.2178x; 1.2178x over previous
#include <cuda_runtime.h>
#include <cuda_fp16.h>
#include <math.h>
#include <stdint.h>

#define NN 30000
#define EE 510000      // 30000*16 + 30000 self loops
#define TT 2
#define KDIM 128       // F_IN == H1 == 128 (GEMM K for both layers)

// ---------------- scratch (device globals; no allocation allowed) ----------------
__device__ __half g_h[(size_t)NN * 256];     // GEMM output t0 (fp16)
__device__ __half g_h2[(size_t)NN * 256];    // GEMM output t1 (fp16)
__device__ float  g_mu0[(size_t)NN * 128];
__device__ float  g_mu1[(size_t)NN * 128];
__device__ float  g_alpha[TT][EE];
__device__ float  g_si[TT][NN];
__device__ float  g_sj[TT][NN];
__device__ float  g_watt[2][128];            // W @ att halves (current layer)
__device__ float  g_invdeg[TT][NN];
__device__ int    g_deg[TT][NN];
__device__ int    g_rowptr[TT][NN + 1];
__device__ int    g_woff[TT][NN];
__device__ int    g_csrc[TT][EE];
__device__ int    g_cdst[TT][EE];
__device__ double g_acc[8];  // [0..3] ixz sums, [4..7] skl sums

// ---------------- helpers ----------------
__device__ __forceinline__ float blockReduceSum(float v, float* sm) {
    int lane = threadIdx.x & 31, wid = threadIdx.x >> 5;
#pragma unroll
    for (int o = 16; o; o >>= 1) v += __shfl_down_sync(0xffffffffu, v, o);
    if (lane == 0) sm[wid] = v;
    __syncthreads();
    int nw = (blockDim.x + 31) >> 5;
    v = (threadIdx.x < nw) ? sm[threadIdx.x] : 0.f;
    if (wid == 0) {
#pragma unroll
        for (int o = 16; o; o >>= 1) v += __shfl_down_sync(0xffffffffu, v, o);
    }
    return v;  // valid on thread 0
}

__device__ __forceinline__ uint32_t f2tf32(float f) {
    uint32_t u;
    asm("cvt.rna.tf32.f32 %0, %1;" : "=r"(u) : "f"(f));
    return u;
}

// ---------------- setup kernels ----------------
__global__ void zero_kernel() {
    int i = blockIdx.x * blockDim.x + threadIdx.x;
    if (i < TT * NN) (&g_deg[0][0])[i] = 0;
    if (i < 8) g_acc[i] = 0.0;
}

__global__ void hist_kernel(const int* __restrict__ ei) {
    int t = blockIdx.y;
    int e = blockIdx.x * blockDim.x + threadIdx.x;
    const int* dst = ei + (size_t)t * 2 * EE + EE;
    if (e < EE) atomicAdd(&g_deg[t][dst[e]], 1);
}

__global__ void scan_kernel() {
    int t = blockIdx.x;
    const int T = 1024;
    int tid = threadIdx.x;
    const int chunk = (NN + T - 1) / T;  // 30
    int s0 = tid * chunk;
    int sum = 0;
    for (int i = 0; i < chunk; i++) {
        int idx = s0 + i;
        if (idx < NN) sum += g_deg[t][idx];
    }
    int lane = tid & 31, wid = tid >> 5;
    int v = sum;
#pragma unroll
    for (int o = 1; o < 32; o <<= 1) {
        int u = __shfl_up_sync(0xffffffffu, v, o);
        if (lane >= o) v += u;
    }
    __shared__ int ws[32];
    if (lane == 31) ws[wid] = v;
    __syncthreads();
    if (wid == 0) {
        int w = ws[lane];
#pragma unroll
        for (int o = 1; o < 32; o <<= 1) {
            int u = __shfl_up_sync(0xffffffffu, w, o);
            if (lane >= o) w += u;
        }
        ws[lane] = w;
    }
    __syncthreads();
    int excl = (v - sum) + (wid > 0 ? ws[wid - 1] : 0);
    int run = excl;
    for (int i = 0; i < chunk; i++) {
        int idx = s0 + i;
        if (idx < NN) {
            int d = g_deg[t][idx];
            g_rowptr[t][idx] = run;
            g_woff[t][idx] = run;
            g_invdeg[t][idx] = 1.0f / (float)d;
            run += d;
        }
    }
    if (tid == T - 1) g_rowptr[t][NN] = run;
}

__global__ void scatter_kernel(const int* __restrict__ ei) {
    int t = blockIdx.y;
    int e = blockIdx.x * blockDim.x + threadIdx.x;
    const int* src = ei + (size_t)t * 2 * EE;
    const int* dst = src + EE;
    if (e < EE) {
        int d = dst[e];
        int pos = atomicAdd(&g_woff[t][d], 1);
        g_csrc[t][pos] = src[e];
        g_cdst[t][pos] = d;
    }
}

// ---------------- TF32 tensor-core GEMM (pipelined, fp16 output) ------------------
// C[M,Ncols] = A[M,128] * B[128,Ncols].  Tile 128x64, 256 threads, 8 warps of 32x32.
#define ASTR 36
#define BSTR 132
#define A_STAGE (128 * ASTR)
#define GEMM_SMEM ((2 * A_STAGE + 64 * BSTR) * 4)
__global__ void __launch_bounds__(256)
gemm_tc_kernel(const float* __restrict__ A0, const float* __restrict__ A1,
               const float* __restrict__ B, __half* __restrict__ C0,
               __half* __restrict__ C1, int M, int Ncols) {
    extern __shared__ float smem[];
    float* Bs = smem + 2 * A_STAGE;
    const float* A = blockIdx.z ? A1 : A0;
    __half* C = blockIdx.z ? C1 : C0;
    int tid = threadIdx.x, lane = tid & 31, wid = tid >> 5;
    int warp_m = wid & 3, warp_n = wid >> 2;
    int row0 = blockIdx.y * 128, col0 = blockIdx.x * 64;
    int sub = lane >> 3, l8 = lane & 7;
    uint32_t as_base = (uint32_t)__cvta_generic_to_shared(smem);
    uint32_t bs_base = as_base + 2 * A_STAGE * 4;

    // B fill: full K, transposed, tf32-converted (one time)
    for (int i = tid; i < 128 * 64; i += 256) {
        int k = i >> 6, n = i & 63;
        Bs[n * BSTR + k] = __uint_as_float(f2tf32(B[(size_t)k * Ncols + col0 + n]));
    }

    // A stage fill via cp.async (4 x 16B per thread); OOB rows: clamped src + zfill
#define FILL_A(buf, k0)                                                              \
    {                                                                                \
        _Pragma("unroll") for (int i = 0; i < 4; i++) {                              \
            int idx = tid + i * 256;                                                 \
            int r = idx >> 3, kc = (idx & 7) * 4;                                    \
            uint32_t dstp = as_base + (uint32_t)(((buf) * A_STAGE + r * ASTR + kc) * 4); \
            int rr = row0 + r;                                                       \
            int ok = rr < M;                                                         \
            int rs = ok ? rr : (M - 1);                                              \
            const float* srcp = A + (size_t)rs * KDIM + (k0) + kc;                   \
            int sz = ok ? 16 : 0;                                                    \
            asm volatile("cp.async.ca.shared.global [%0], [%1], 16, %2;"             \
                         :: "r"(dstp), "l"(srcp), "r"(sz));                          \
        }                                                                            \
    }

    FILL_A(0, 0);
    asm volatile("cp.async.commit_group;");

    float acc[2][4][4] = {};
    int a_r = warp_m * 32 + (sub & 1) * 8 + l8;
    int a_c = (sub >> 1) * 4;
    int b_r = warp_n * 32 + (sub >> 1) * 8 + l8;
    int b_c = (sub & 1) * 4;

    int s = 0;
    for (int k0 = 0; k0 < KDIM; k0 += 32, s ^= 1) {
        if (k0 + 32 < KDIM) {
            FILL_A(s ^ 1, k0 + 32);
            asm volatile("cp.async.commit_group;");
            asm volatile("cp.async.wait_group 1;");
        } else {
            asm volatile("cp.async.wait_group 0;");
        }
        __syncthreads();
        int abase = s * A_STAGE;
#pragma unroll
        for (int kk = 0; kk < 32; kk += 8) {
            uint32_t a[2][4], b[2][4];
#pragma unroll
            for (int im = 0; im < 2; im++) {
                uint32_t addr = as_base + (uint32_t)((abase + (a_r + im * 16) * ASTR + a_c + kk) * 4);
                asm volatile("ldmatrix.sync.aligned.m8n8.x4.shared.b16 {%0,%1,%2,%3}, [%4];"
                             : "=r"(a[im][0]), "=r"(a[im][1]), "=r"(a[im][2]), "=r"(a[im][3])
                             : "r"(addr));
            }
#pragma unroll
            for (int im = 0; im < 2; im++)
#pragma unroll
                for (int j = 0; j < 4; j++)
                    a[im][j] = f2tf32(__uint_as_float(a[im][j]));
#pragma unroll
            for (int p = 0; p < 2; p++) {
                uint32_t addr = bs_base + (uint32_t)(((b_r + p * 16) * BSTR + b_c + k0 + kk) * 4);
                asm volatile("ldmatrix.sync.aligned.m8n8.x4.shared.b16 {%0,%1,%2,%3}, [%4];"
                             : "=r"(b[p][0]), "=r"(b[p][1]), "=r"(b[p][2]), "=r"(b[p][3])
                             : "r"(addr));
            }
#pragma unroll
            for (int im = 0; im < 2; im++)
#pragma unroll
                for (int in = 0; in < 4; in++) {
                    uint32_t b0 = b[in >> 1][(in & 1) * 2 + 0];
                    uint32_t b1 = b[in >> 1][(in & 1) * 2 + 1];
                    asm volatile(
                        "mma.sync.aligned.m16n8k8.row.col.f32.tf32.tf32.f32 "
                        "{%0,%1,%2,%3}, {%4,%5,%6,%7}, {%8,%9}, {%0,%1,%2,%3};"
                        : "+f"(acc[im][in][0]), "+f"(acc[im][in][1]),
                          "+f"(acc[im][in][2]), "+f"(acc[im][in][3])
                        : "r"(a[im][0]), "r"(a[im][1]), "r"(a[im][2]), "r"(a[im][3]),
                          "r"(b0), "r"(b1));
                }
        }
        __syncthreads();
    }
#pragma unroll
    for (int im = 0; im < 2; im++) {
        int r = row0 + warp_m * 32 + im * 16 + (lane >> 2);
#pragma unroll
        for (int in = 0; in < 4; in++) {
            int c = col0 + warp_n * 32 + in * 8 + (lane & 3) * 2;
            if (r < M)
                *(__half2*)&C[(size_t)r * Ncols + c] =
                    __floats2half2_rn(acc[im][in][0], acc[im][in][1]);
            if (r + 8 < M)
                *(__half2*)&C[(size_t)(r + 8) * Ncols + c] =
                    __floats2half2_rn(acc[im][in][2], acc[im][in][3]);
        }
    }
}

// ---------------- W @ att precompute ----------------
__global__ void watt_kernel(const float* __restrict__ W, const float* __restrict__ att, int TC) {
    int k = threadIdx.x;  // 0..127
    const float* row = W + (size_t)k * TC;
    float a = 0.f, b = 0.f;
    for (int c = 0; c < TC; c++) {
        float v = row[c];
        a = fmaf(v, att[c], a);
        b = fmaf(v, att[TC + c], b);
    }
    g_watt[0][k] = a;
    g_watt[1][k] = b;
}

// ---------------- per-node attention scores (both snapshots) ----------------
__global__ void scores_x_kernel(const float4* __restrict__ x0, const float4* __restrict__ x1) {
    int t = blockIdx.y;
    const float4* x4 = t ? x1 : x0;
    int gw = (blockIdx.x * blockDim.x + threadIdx.x) >> 5;
    int lane = threadIdx.x & 31;
    if (gw >= NN) return;
    float4 v = x4[(size_t)gw * 32 + lane];
    const float4 wa = *(const float4*)&g_watt[0][lane * 4];
    const float4 wb = *(const float4*)&g_watt[1][lane * 4];
    float a = v.x * wa.x + v.y * wa.y + v.z * wa.z + v.w * wa.w;
    float b = v.x * wb.x + v.y * wb.y + v.z * wb.z + v.w * wb.w;
#pragma unroll
    for (int o = 16; o; o >>= 1) {
        a += __shfl_down_sync(0xffffffffu, a, o);
        b += __shfl_down_sync(0xffffffffu, b, o);
    }
    if (lane == 0) {
        g_si[t][gw] = a;
        g_sj[t][gw] = b;
    }
}

// ---------------- per-edge alpha + skl (both snapshots) ----------------
__global__ void alpha_kernel(double* __restrict__ skl_base) {
    __shared__ float s_red[32];
    int t = blockIdx.y;
    int e = blockIdx.x * blockDim.x + threadIdx.x;
    float skl = 0.f;
    if (e < EE) {
        int d = g_cdst[t][e], s = g_csrc[t][e];
        float l = g_si[t][d] + g_sj[t][s];
        l = l > 0.f ? l : 0.2f * l;
        float p = 1.f / (1.f + expf(-l));
        p = fminf(fmaxf(p, 0.01f), 0.99f);
        g_alpha[t][e] = p * g_invdeg[t][d];
        float q = 1.0f / (1.0f + expf(-(1.0f / 15.0f)));
        skl = p * (logf(p) - logf(q)) + (1.f - p) * (logf(1.f - p) - logf(1.f - q));
    }
    float tot = blockReduceSum(skl, s_red);
    if (threadIdx.x == 0) atomicAdd(skl_base + t, (double)tot);
}

// ---------------- aggregation + KL epilogue (both snapshots; fp16 h) --------------
template <int C>
__global__ void agg_kernel(const __half* __restrict__ h0, const __half* __restrict__ h1,
                           const float* __restrict__ bias, float* __restrict__ out0,
                           float* __restrict__ out1, double* __restrict__ ixz_base) {
    constexpr int TC = 2 * C;
    __shared__ float s_alpha[TC];
    __shared__ int s_src[TC];
    __shared__ float s_std[C];
    __shared__ float s_red[32];
    int n = blockIdx.x, t = blockIdx.y, tid = threadIdx.x;
    const __half* h = t ? h1 : h0;
    const float* alpha = g_alpha[t];
    const int* csrc = g_csrc[t];
    float* mu_out = t ? out1 : out0;
    int start = g_rowptr[t][n], end = g_rowptr[t][n + 1];
    float acc = 0.f;
    for (int base = start; base < end; base += TC) {
        int cnt = min(TC, end - base);
        if (tid < cnt) {
            s_alpha[tid] = alpha[base + tid];
            s_src[tid] = csrc[base + tid];
        }
        __syncthreads();
        for (int i = 0; i < cnt; i++)
            acc = fmaf(s_alpha[i], __half2float(h[(size_t)s_src[i] * TC + tid]), acc);
        __syncthreads();
    }
    acc += bias[tid];
    if (tid >= C) {
        float x = acc;
        s_std[tid - C] = fmaxf(x, 0.f) + log1pf(expf(-fabsf(x))) + 1e-10f;
    }
    __syncthreads();
    float kl = 0.f;
    if (tid < C) {
        float mu = acc, sd = s_std[tid];
        kl = -logf(sd) + 0.5f * fmaf(sd, sd, mu * mu) - 0.5f;
        mu_out[(size_t)n * C + tid] = mu;
    }
    float tot = blockReduceSum(kl, s_red);
    if (tid == 0) atomicAdd(ixz_base + t, (double)tot);
}

// ---------------- temporal fusion / activations ----------------
__global__ void fuse1_kernel() {
    int i = blockIdx.x * blockDim.x + threadIdx.x;
    if (i < NN * 128) {
        float m0 = g_mu0[i], m1 = g_mu1[i];
        g_mu1[i] = fmaxf(0.4f * m0 + 0.2f * m1, 0.f);
        g_mu0[i] = fmaxf(m0, 0.f);
    }
}

__global__ void fuse2_kernel(float* __restrict__ out) {
    int i = blockIdx.x * blockDim.x + threadIdx.x;
    if (i < NN * 64) out[NN * 64 + i] = 0.4f * out[i] + 0.2f * g_mu1[i];
}

__global__ void finalize_kernel(float* __restrict__ out, int out_size) {
    double ixz = (g_acc[0] + g_acc[1] + g_acc[2] + g_acc[3]) / (4.0 * (double)NN);
    double skl = (g_acc[4] + g_acc[5] + g_acc[6] + g_acc[7]) / (4.0 * (double)EE);
    out[out_size - 2] = (float)ixz;
    out[out_size - 1] = (float)skl;
}

// ---------------- launch ----------------
extern "C" void kernel_launch(void* const* d_in, const int* in_sizes, int n_in,
                              void* d_out, int out_size) {
    const float* x_all = (const float*)d_in[0];   // [T, N, 128]
    const int* ei = (const int*)d_in[1];          // [T, 2, E]
    const float* W1 = (const float*)d_in[2];      // [128, 256]
    const float* att1 = (const float*)d_in[3];    // [512]
    const float* b1 = (const float*)d_in[4];      // [256]
    const float* W2 = (const float*)d_in[5];      // [128, 128]
    const float* att2 = (const float*)d_in[6];    // [256]
    const float* b2 = (const float*)d_in[7];      // [128]
    float* out = (float*)d_out;

    (void)cudaFuncSetAttribute(gemm_tc_kernel,
                               cudaFuncAttributeMaxDynamicSharedMemorySize, GEMM_SMEM);

    __half *p_h, *p_h2;
    float *p_mu0, *p_mu1;
    double* p_acc;
    cudaGetSymbolAddress((void**)&p_h, g_h);
    cudaGetSymbolAddress((void**)&p_h2, g_h2);
    cudaGetSymbolAddress((void**)&p_mu0, g_mu0);
    cudaGetSymbolAddress((void**)&p_mu1, g_mu1);
    cudaGetSymbolAddress((void**)&p_acc, g_acc);

    const int EB = (EE + 255) / 256;
    const int SB = (NN * 32 + 255) / 256;
    const int MB = (NN + 127) / 128;  // 235

    zero_kernel<<<(TT * NN + 255) / 256, 256>>>();                        // 0
    hist_kernel<<<dim3(EB, 2), 256>>>(ei);                                // 1
    scan_kernel<<<2, 1024>>>();                                           // 2
    gemm_tc_kernel<<<dim3(4, MB, 2), 256, GEMM_SMEM>>>(                   // 3 <- profiled
        x_all, x_all + (size_t)NN * KDIM, W1, p_h, p_h2, NN, 256);
    scatter_kernel<<<dim3(EB, 2), 256>>>(ei);                             // 4
    watt_kernel<<<1, 128>>>(W1, att1, 256);                               // 5
    scores_x_kernel<<<dim3(SB, 2), 256>>>(                                // 6
        (const float4*)x_all, (const float4*)(x_all + (size_t)NN * KDIM));
    alpha_kernel<<<dim3(EB, 2), 256>>>(p_acc + 4);                        // 7
    agg_kernel<128><<<dim3(NN, 2), 256>>>(p_h, p_h2, b1, p_mu0, p_mu1, p_acc + 0);  // 8
    fuse1_kernel<<<(NN * 128 + 255) / 256, 256>>>();                      // 9

    watt_kernel<<<1, 128>>>(W2, att2, 128);                               // 10
    gemm_tc_kernel<<<dim3(2, MB, 2), 256, GEMM_SMEM>>>(                   // 11
        p_mu0, p_mu1, W2, p_h, p_h2, NN, 128);
    scores_x_kernel<<<dim3(SB, 2), 256>>>((const float4*)p_mu0, (const float4*)p_mu1);  // 12
    alpha_kernel<<<dim3(EB, 2), 256>>>(p_acc + 6);                        // 13
    agg_kernel<64><<<dim3(NN, 2), 128>>>(p_h, p_h2, b2, out, p_mu1, p_acc + 2);  // 14
    fuse2_kernel<<<(NN * 64 + 255) / 256, 256>>>(out);                    // 15
    finalize_kernel<<<1, 1>>>(out, out_size);                             // 16
}